// round 6
// baseline (speedup 1.0000x reference)
#include <cuda_runtime.h>
#include <cuda_fp16.h>
#include <math.h>

// ---------------- scratch (no allocation allowed; __device__ globals) --------
#define MAX_N 100000
__device__ float  g_proj[MAX_N * 32];  // [n][0:16]=z@W1a, [n][16:32]=z@W1b+b1 (12.8 MB)
__device__ float4 g_Wfmt[32 * 32];     // [s][l] = {W1c[4s+j][l], j=0..3} (16 KB)
__device__ uint2  g_zh[MAX_N * 32];    // z in fp16, linear per-node 256B rows (25.6 MB)

// packed f32x2 FMA (Blackwell FFMA2 — PTX-only, ptxas never auto-fuses)
#define FMA_F32X2(acc, a, b) \
    asm("fma.rn.f32x2 %0, %1, %2, %0;" : "+l"(acc) : "l"(a), "l"(b))

__device__ __forceinline__ float2 cvt_h2(unsigned u) {
    __half2 h = *reinterpret_cast<__half2*>(&u);
    return __half22float2(h);
}

// ---------------- kernel 0: one-time W1 reformat into [s][l][4] --------------
__global__ void prep_W_kernel(const float* __restrict__ W1) {
    int idx = blockIdx.x * blockDim.x + threadIdx.x;   // flat float index 0..4095
    if (idx >= 32 * 128) return;
    int j = idx & 3;
    int l = (idx >> 2) & 31;
    int s = idx >> 7;
    int k = 4 * s + j;
    float v = (l < 16) ? W1[k * 16 + l] : W1[(128 + k) * 16 + (l - 16)];
    ((float*)g_Wfmt)[idx] = v;
}

// ---------------- kernel 1: per-node projection + fp16 z emission -----------
// 256 thr = 8 warps; warp computes 8 nodes x 32 cols (lane = col).
// No z staging: broadcast __ldg reads pipeline directly into the FMA loop
// (each 128B z line is L1-hot after first warp touch). smem = 16KB weights only.
// Also emits the fp16 copy of z (read already paid for).
#define PROJ_BLOCK 256
#define NODES_PER_WARP 8
#define NODES_PER_BLOCK 64   // 8 warps * 8 nodes

__global__ __launch_bounds__(PROJ_BLOCK) void proj_kernel(
    const float* __restrict__ z, const float* __restrict__ b1, int N)
{
    __shared__ float4 sW[32 * 32];                // 16 KB, [s*32 + lane] = k-quad
    const int tid = threadIdx.x;

    #pragma unroll
    for (int i = 0; i < 1024 / PROJ_BLOCK; i++)   // coalesced 16KB weight copy
        sW[tid + i * PROJ_BLOCK] = g_Wfmt[tid + i * PROJ_BLOCK];
    __syncthreads();

    const int warp = tid >> 5;
    const int lane = tid & 31;                    // = output column c
    const int nb = blockIdx.x * NODES_PER_BLOCK + warp * NODES_PER_WARP;

    const ulonglong2* z2 = (const ulonglong2*)z;  // 32 x 16B per node row
    size_t base[NODES_PER_WARP];
    #pragma unroll
    for (int n = 0; n < NODES_PER_WARP; n++)
        base[n] = (size_t)min(nb + n, N - 1) * 32;

    const ulonglong2* sW2 = (const ulonglong2*)sW;
    unsigned long long acc[NODES_PER_WARP];       // packed {sum_even, sum_odd}
    #pragma unroll
    for (int n = 0; n < NODES_PER_WARP; n++) acc[n] = 0ull;

    #pragma unroll 8
    for (int s = 0; s < 32; s++) {
        ulonglong2 wv = sW2[s * 32 + lane];       // conflict-free LDS.128
        #pragma unroll
        for (int n = 0; n < NODES_PER_WARP; n++) {
            ulonglong2 zv = __ldg(z2 + base[n] + s);   // broadcast, L1-hot
            FMA_F32X2(acc[n], zv.x, wv.x);
            FMA_F32X2(acc[n], zv.y, wv.y);
        }
    }

    // fold b1 into the col-side (cols 16..31) so edge kernel skips it
    const float bias = (lane >= 16) ? __ldg(b1 + lane - 16) : 0.f;
    const float4* z4 = (const float4*)z;

    #pragma unroll
    for (int n = 0; n < NODES_PER_WARP; n++) {
        int node = nb + n;
        if (node < N) {
            float2 p = *reinterpret_cast<float2*>(&acc[n]);
            g_proj[(size_t)node * 32 + lane] = p.x + p.y + bias;   // coalesced

            // fp16 emission: lane owns floats [4l..4l+4) of the node row (L1 hit)
            float4 v = __ldg(z4 + (size_t)node * 32 + lane);
            __half2 h0 = __floats2half2_rn(v.x, v.y);
            __half2 h1 = __floats2half2_rn(v.z, v.w);
            uint2 pk;
            pk.x = *reinterpret_cast<unsigned*>(&h0);
            pk.y = *reinterpret_cast<unsigned*>(&h1);
            g_zh[(size_t)node * 32 + lane] = pk;                   // coalesced 256B
        }
    }
}

// ---------------- kernel 2: per-edge dual head (fp16 dot, 2 edges/warp) ------
// 16 lanes per edge. Each lane loads 16B (8 halves) of z_row and z_col
// (256B per node row — half the f32 traffic), converts to f32, FMA-accumulates.
// The 16 lanes own the 16 hidden units of the MLP head (f32 proj, 64B/side).
__global__ __launch_bounds__(256) void edge_kernel(
    const int* __restrict__ ei,            // int32 (jax x64 disabled)
    const float* __restrict__ W2,
    const float* __restrict__ b2,
    float* __restrict__ out,
    int E)
{
    const int group = (int)((blockIdx.x * blockDim.x + threadIdx.x) >> 4);  // edge id
    const int l = threadIdx.x & 15;
    const bool valid = (group < E);
    const int e = valid ? group : (E - 1);        // clamp; keep warp converged

    const int row = __ldg(ei + e);
    const int col = __ldg(ei + (size_t)E + e);

    const uint4* zh = (const uint4*)g_zh;         // 16 x 16B per node row
    uint4 A = __ldg(zh + (size_t)row * 16 + l);
    uint4 B = __ldg(zh + (size_t)col * 16 + l);

    float2 a0 = cvt_h2(A.x), a1 = cvt_h2(A.y), a2 = cvt_h2(A.z), a3 = cvt_h2(A.w);
    float2 c0 = cvt_h2(B.x), c1 = cvt_h2(B.y), c2 = cvt_h2(B.z), c3 = cvt_h2(B.w);

    float dot = a0.x * c0.x + a0.y * c0.y
              + a1.x * c1.x + a1.y * c1.y
              + a2.x * c2.x + a2.y * c2.y
              + a3.x * c3.x + a3.y * c3.y;

    // MLP head: h_l = projA[row][l] + (projB[col][l] + b1[l])   (b1 pre-folded)
    float pa = g_proj[row * 32 + l];
    float pb = g_proj[col * 32 + 16 + l];
    float h  = fmaxf(pa + pb, 0.f);
    float t  = h * __ldg(W2 + l);

    #pragma unroll
    for (int off = 8; off; off >>= 1) {
        dot += __shfl_xor_sync(0xFFFFFFFFu, dot, off);
        t   += __shfl_xor_sync(0xFFFFFFFFu, t, off);
    }

    if (l == 0 && valid) {
        out[e] = dot;
        float x = t + __ldg(b2);
        // softplus = max(x,0) + log1p(exp(-|x|))
        out[(size_t)E + e] = fmaxf(x, 0.f) + log1pf(__expf(-fabsf(x)));
    }
}

// ---------------- launch ----------------------------------------------------
extern "C" void kernel_launch(void* const* d_in, const int* in_sizes, int n_in,
                              void* d_out, int out_size) {
    const float* z  = (const float*)d_in[0];      // [N,128] f32
    const int*   ei = (const int*)d_in[1];        // [2,E] int32
    const float* W1 = (const float*)d_in[2];      // [256,16]
    const float* b1 = (const float*)d_in[3];      // [16]
    const float* W2 = (const float*)d_in[4];      // [16,1]
    const float* b2 = (const float*)d_in[5];      // [1]
    float* out = (float*)d_out;                   // [2E]: adj_logits | weights

    const int N = in_sizes[0] / 128;
    const int E = in_sizes[1] / 2;

    prep_W_kernel<<<(32 * 128 + 255) / 256, 256>>>(W1);
    proj_kernel<<<(N + NODES_PER_BLOCK - 1) / NODES_PER_BLOCK, PROJ_BLOCK>>>(z, b1, N);
    edge_kernel<<<((size_t)E * 16 + 255) / 256, 256>>>(ei, W2, b2, out, E);
}

// round 7
// speedup vs baseline: 1.2874x; 1.2874x over previous
#include <cuda_runtime.h>
#include <cuda_fp16.h>
#include <math.h>

// ---------------- scratch (no allocation allowed; __device__ globals) --------
#define MAX_N 100000
__device__ float  g_proj[MAX_N * 32];  // [n][0:16]=z@W1a, [n][16:32]=z@W1b+b1 (12.8 MB)
__device__ float4 g_Wfmt[32 * 32];     // [s][l] = {W1c[4s+j][l], j=0..3} (16 KB)
__device__ uint2  g_zh[MAX_N * 32];    // z in fp16, 256B per node row (25.6 MB)

// packed f32x2 FMA (Blackwell FFMA2 — PTX-only, ptxas never auto-fuses)
#define FMA_F32X2(acc, a, b) \
    asm("fma.rn.f32x2 %0, %1, %2, %0;" : "+l"(acc) : "l"(a), "l"(b))

__device__ __forceinline__ float2 cvt_h2(unsigned u) {
    __half2 h = *reinterpret_cast<__half2*>(&u);
    return __half22float2(h);
}

// ---------------- kernel 0: one-time W1 reformat into [s][l][4] --------------
__global__ void prep_W_kernel(const float* __restrict__ W1) {
    int idx = blockIdx.x * blockDim.x + threadIdx.x;   // flat float index 0..4095
    if (idx >= 32 * 128) return;
    int j = idx & 3;
    int l = (idx >> 2) & 31;
    int s = idx >> 7;
    int k = 4 * s + j;
    float v = (l < 16) ? W1[k * 16 + l] : W1[(128 + k) * 16 + (l - 16)];
    ((float*)g_Wfmt)[idx] = v;
}

// ---------------- kernel 1: per-node projection + fp16 z emission -----------
// R5-proven structure: 256 thr = 8 warps; z tile staged in shared (coalesced),
// weights in sW[s][lane] (conflict-free LDS.128), f32x2 packed FMA mainloop,
// b1 folded into cols 16..31 at store. fp16 copy of z emitted FROM sZ (no
// extra global reads).
#define PROJ_BLOCK 256
#define NODES_PER_WARP 8
#define NODES_PER_BLOCK 64   // 8 warps * 8 nodes

__global__ __launch_bounds__(PROJ_BLOCK, 2) void proj_kernel(
    const float* __restrict__ z, const float* __restrict__ b1, int N)
{
    __shared__ float4 sZ[NODES_PER_BLOCK * 32];   // 64 nodes x 128 f32 = 32 KB
    __shared__ float4 sW[32 * 32];                // 16 KB, [s*32 + lane] = k-quad
    const int tid = threadIdx.x;
    const int node0 = blockIdx.x * NODES_PER_BLOCK;

    #pragma unroll
    for (int i = 0; i < 1024 / PROJ_BLOCK; i++)   // coalesced 16KB weight copy
        sW[tid + i * PROJ_BLOCK] = g_Wfmt[tid + i * PROJ_BLOCK];

    const float4* z4 = (const float4*)z;
    #pragma unroll
    for (int i = 0; i < (NODES_PER_BLOCK * 32) / PROJ_BLOCK; i++) {
        int idx = tid + i * PROJ_BLOCK;
        int n = node0 + (idx >> 5);
        sZ[idx] = (n < N) ? z4[(size_t)n * 32 + (idx & 31)]
                          : make_float4(0.f, 0.f, 0.f, 0.f);
    }
    __syncthreads();

    const int warp = tid >> 5;
    const int lane = tid & 31;                       // = output column c
    const ulonglong2* zbase = (const ulonglong2*)(sZ + (warp * NODES_PER_WARP) * 32);
    const ulonglong2* sW2   = (const ulonglong2*)sW;

    unsigned long long acc[NODES_PER_WARP];          // packed {sum_even, sum_odd}
    #pragma unroll
    for (int n = 0; n < NODES_PER_WARP; n++) acc[n] = 0ull;

    #pragma unroll 8
    for (int s = 0; s < 32; s++) {
        ulonglong2 wv = sW2[s * 32 + lane];          // conflict-free LDS.128
        #pragma unroll
        for (int n = 0; n < NODES_PER_WARP; n++) {
            ulonglong2 zv = zbase[n * 32 + s];       // LDS.128 broadcast
            FMA_F32X2(acc[n], zv.x, wv.x);
            FMA_F32X2(acc[n], zv.y, wv.y);
        }
    }

    // fold b1 into the col-side (cols 16..31) so edge kernel skips it
    const float bias = (lane >= 16) ? __ldg(b1 + lane - 16) : 0.f;

    #pragma unroll
    for (int n = 0; n < NODES_PER_WARP; n++) {
        int node = node0 + warp * NODES_PER_WARP + n;
        if (node < N) {
            float2 p = *reinterpret_cast<float2*>(&acc[n]);
            g_proj[(size_t)node * 32 + lane] = p.x + p.y + bias;   // coalesced
        }
    }

    // fp16 emission from sZ: thread handles 8 float4 quads (coalesced 8B stores)
    #pragma unroll
    for (int i = 0; i < (NODES_PER_BLOCK * 32) / PROJ_BLOCK; i++) {
        int idx = tid + i * PROJ_BLOCK;
        int node = node0 + (idx >> 5);
        if (node < N) {
            float4 v = sZ[idx];
            __half2 h0 = __floats2half2_rn(v.x, v.y);
            __half2 h1 = __floats2half2_rn(v.z, v.w);
            uint2 pk;
            pk.x = *reinterpret_cast<unsigned*>(&h0);
            pk.y = *reinterpret_cast<unsigned*>(&h1);
            g_zh[(size_t)node0 * 32 + idx] = pk;
        }
    }
}

// ---------------- kernel 2: per-edge dual head (fp16 dot, 2 edges/warp) ------
// 16 lanes per edge. Each lane loads 16B (8 halves) of z_row and z_col
// (256B per node row — half the f32 line count), converts to f32, accumulates.
// The 16 lanes own the 16 hidden units of the MLP head (f32 proj, 64B/side).
__global__ __launch_bounds__(256) void edge_kernel(
    const int* __restrict__ ei,            // int32 (jax x64 disabled)
    const float* __restrict__ W2,
    const float* __restrict__ b2,
    float* __restrict__ out,
    int E)
{
    const int group = (int)((blockIdx.x * blockDim.x + threadIdx.x) >> 4);  // edge id
    const int l = threadIdx.x & 15;
    const bool valid = (group < E);
    const int e = valid ? group : (E - 1);        // clamp; keep warp converged

    const int row = __ldg(ei + e);
    const int col = __ldg(ei + (size_t)E + e);

    const uint4* zh = (const uint4*)g_zh;         // 16 x 16B per node row
    uint4 A = __ldg(zh + (size_t)row * 16 + l);
    uint4 B = __ldg(zh + (size_t)col * 16 + l);

    float2 a0 = cvt_h2(A.x), a1 = cvt_h2(A.y), a2 = cvt_h2(A.z), a3 = cvt_h2(A.w);
    float2 c0 = cvt_h2(B.x), c1 = cvt_h2(B.y), c2 = cvt_h2(B.z), c3 = cvt_h2(B.w);

    float dot = a0.x * c0.x + a0.y * c0.y
              + a1.x * c1.x + a1.y * c1.y
              + a2.x * c2.x + a2.y * c2.y
              + a3.x * c3.x + a3.y * c3.y;

    // MLP head: h_l = projA[row][l] + (projB[col][l] + b1[l])   (b1 pre-folded)
    float pa = g_proj[row * 32 + l];
    float pb = g_proj[col * 32 + 16 + l];
    float h  = fmaxf(pa + pb, 0.f);
    float t  = h * __ldg(W2 + l);

    #pragma unroll
    for (int off = 8; off; off >>= 1) {
        dot += __shfl_xor_sync(0xFFFFFFFFu, dot, off);
        t   += __shfl_xor_sync(0xFFFFFFFFu, t, off);
    }

    if (l == 0 && valid) {
        out[e] = dot;
        float x = t + __ldg(b2);
        // softplus = max(x,0) + log1p(exp(-|x|))
        out[(size_t)E + e] = fmaxf(x, 0.f) + log1pf(__expf(-fabsf(x)));
    }
}

// ---------------- launch ----------------------------------------------------
extern "C" void kernel_launch(void* const* d_in, const int* in_sizes, int n_in,
                              void* d_out, int out_size) {
    const float* z  = (const float*)d_in[0];      // [N,128] f32
    const int*   ei = (const int*)d_in[1];        // [2,E] int32
    const float* W1 = (const float*)d_in[2];      // [256,16]
    const float* b1 = (const float*)d_in[3];      // [16]
    const float* W2 = (const float*)d_in[4];      // [16,1]
    const float* b2 = (const float*)d_in[5];      // [1]
    float* out = (float*)d_out;                   // [2E]: adj_logits | weights

    const int N = in_sizes[0] / 128;
    const int E = in_sizes[1] / 2;

    prep_W_kernel<<<(32 * 128 + 255) / 256, 256>>>(W1);
    proj_kernel<<<(N + NODES_PER_BLOCK - 1) / NODES_PER_BLOCK, PROJ_BLOCK>>>(z, b1, N);
    edge_kernel<<<((size_t)E * 16 + 255) / 256, 256>>>(ei, W2, b2, out, E);
}

// round 8
// speedup vs baseline: 1.5627x; 1.2138x over previous
#include <cuda_runtime.h>
#include <cuda_fp16.h>
#include <math.h>

// ---------------- scratch (no allocation allowed; __device__ globals) --------
#define MAX_N 100000
__device__ float  g_proj[MAX_N * 32];  // [n][0:16]=z@W1a, [n][16:32]=z@W1b+b1 (12.8 MB)
__device__ uint2  g_zh[MAX_N * 32];    // z in fp16, 256B per node row (25.6 MB)

// packed f32x2 FMA (Blackwell FFMA2 — PTX-only, ptxas never auto-fuses)
#define FMA_F32X2(acc, a, b) \
    asm("fma.rn.f32x2 %0, %1, %2, %0;" : "+l"(acc) : "l"(a), "l"(b))

__device__ __forceinline__ float2 cvt_h2(unsigned u) {
    __half2 h = *reinterpret_cast<__half2*>(&u);
    return __half22float2(h);
}

// ---------------- kernel 1: per-node projection + fp16 z emission -----------
// 256 thr = 8 warps; warp computes 8 nodes x 32 cols (lane = col).
// W1 reformat done in-block: coalesced LDG into sZ staging, LDS-scatter into
// sW[s][lane] float4 layout (conflict-free LDS.128 in the mainloop).
// z tile staged in sZ (coalesced), f32x2 packed FMA mainloop, b1 folded into
// cols 16..31, fp16 copy of z emitted from sZ.
#define PROJ_BLOCK 256
#define NODES_PER_WARP 8
#define NODES_PER_BLOCK 64   // 8 warps * 8 nodes

__global__ __launch_bounds__(PROJ_BLOCK, 2) void proj_kernel(
    const float* __restrict__ z, const float* __restrict__ W1,
    const float* __restrict__ b1, int N)
{
    __shared__ float4 sZ[NODES_PER_BLOCK * 32];   // 32 KB (also W1 staging)
    __shared__ float4 sW[32 * 32];                // 16 KB, [s*32 + lane] = k-quad
    const int tid = threadIdx.x;
    const int node0 = blockIdx.x * NODES_PER_BLOCK;

    // stage W1 raw (16KB, coalesced LDG) into sZ, then reformat via LDS scatter
    float* sraw = (float*)sZ;
    #pragma unroll
    for (int i = 0; i < 4096 / PROJ_BLOCK; i++)
        sraw[tid + i * PROJ_BLOCK] = W1[tid + i * PROJ_BLOCK];
    __syncthreads();
    #pragma unroll
    for (int i = 0; i < 4096 / PROJ_BLOCK; i++) {
        int idx = tid + i * PROJ_BLOCK;
        int j = idx & 3;
        int l = (idx >> 2) & 31;
        int s = idx >> 7;
        int k = 4 * s + j;
        ((float*)sW)[idx] = (l < 16) ? sraw[k * 16 + l]
                                     : sraw[(128 + k) * 16 + (l - 16)];
    }
    __syncthreads();

    const float4* z4 = (const float4*)z;
    #pragma unroll
    for (int i = 0; i < (NODES_PER_BLOCK * 32) / PROJ_BLOCK; i++) {
        int idx = tid + i * PROJ_BLOCK;
        int n = node0 + (idx >> 5);
        sZ[idx] = (n < N) ? z4[(size_t)n * 32 + (idx & 31)]
                          : make_float4(0.f, 0.f, 0.f, 0.f);
    }
    __syncthreads();

    const int warp = tid >> 5;
    const int lane = tid & 31;                       // = output column c
    const ulonglong2* zbase = (const ulonglong2*)(sZ + (warp * NODES_PER_WARP) * 32);
    const ulonglong2* sW2   = (const ulonglong2*)sW;

    unsigned long long acc[NODES_PER_WARP];          // packed {sum_even, sum_odd}
    #pragma unroll
    for (int n = 0; n < NODES_PER_WARP; n++) acc[n] = 0ull;

    #pragma unroll 8
    for (int s = 0; s < 32; s++) {
        ulonglong2 wv = sW2[s * 32 + lane];          // conflict-free LDS.128
        #pragma unroll
        for (int n = 0; n < NODES_PER_WARP; n++) {
            ulonglong2 zv = zbase[n * 32 + s];       // LDS.128 broadcast
            FMA_F32X2(acc[n], zv.x, wv.x);
            FMA_F32X2(acc[n], zv.y, wv.y);
        }
    }

    // fold b1 into the col-side (cols 16..31) so edge kernel skips it
    const float bias = (lane >= 16) ? __ldg(b1 + lane - 16) : 0.f;

    #pragma unroll
    for (int n = 0; n < NODES_PER_WARP; n++) {
        int node = node0 + warp * NODES_PER_WARP + n;
        if (node < N) {
            float2 p = *reinterpret_cast<float2*>(&acc[n]);
            g_proj[(size_t)node * 32 + lane] = p.x + p.y + bias;   // coalesced
        }
    }

    // fp16 emission from sZ (coalesced 8B stores)
    #pragma unroll
    for (int i = 0; i < (NODES_PER_BLOCK * 32) / PROJ_BLOCK; i++) {
        int idx = tid + i * PROJ_BLOCK;
        int node = node0 + (idx >> 5);
        if (node < N) {
            float4 v = sZ[idx];
            __half2 h0 = __floats2half2_rn(v.x, v.y);
            __half2 h1 = __floats2half2_rn(v.z, v.w);
            uint2 pk;
            pk.x = *reinterpret_cast<unsigned*>(&h0);
            pk.y = *reinterpret_cast<unsigned*>(&h1);
            g_zh[(size_t)node0 * 32 + idx] = pk;
        }
    }
}

// ---------------- kernel 2: per-edge dual head (fp16 dot, 4 edges/warp) ------
// 8 lanes per edge. Each lane loads 2x16B of z_row and z_col fp16 (full 256B
// row per side across the group), converts to f32, accumulates 16 products.
// Each lane owns 2 hidden units of the MLP head (float2 proj loads).
// 3 xor-shuffle rounds reduce both dot and t within the 8-lane group.
__global__ __launch_bounds__(256) void edge_kernel(
    const int* __restrict__ ei,            // int32 (jax x64 disabled)
    const float* __restrict__ W2,
    const float* __restrict__ b2,
    float* __restrict__ out,
    int E)
{
    const int group = (int)((blockIdx.x * blockDim.x + threadIdx.x) >> 3);  // edge id
    const int l = threadIdx.x & 7;
    const bool valid = (group < E);
    const int e = valid ? group : (E - 1);        // clamp; keep warp converged

    const int row = __ldg(ei + e);
    const int col = __ldg(ei + (size_t)E + e);

    const uint4* zh = (const uint4*)g_zh;         // 16 x 16B per node row
    uint4 A0 = __ldg(zh + (size_t)row * 16 + l);
    uint4 A1 = __ldg(zh + (size_t)row * 16 + 8 + l);
    uint4 B0 = __ldg(zh + (size_t)col * 16 + l);
    uint4 B1 = __ldg(zh + (size_t)col * 16 + 8 + l);

    float2 a, b;
    float dot;
    a = cvt_h2(A0.x); b = cvt_h2(B0.x); dot  = a.x * b.x + a.y * b.y;
    a = cvt_h2(A0.y); b = cvt_h2(B0.y); dot += a.x * b.x + a.y * b.y;
    a = cvt_h2(A0.z); b = cvt_h2(B0.z); dot += a.x * b.x + a.y * b.y;
    a = cvt_h2(A0.w); b = cvt_h2(B0.w); dot += a.x * b.x + a.y * b.y;
    a = cvt_h2(A1.x); b = cvt_h2(B1.x); dot += a.x * b.x + a.y * b.y;
    a = cvt_h2(A1.y); b = cvt_h2(B1.y); dot += a.x * b.x + a.y * b.y;
    a = cvt_h2(A1.z); b = cvt_h2(B1.z); dot += a.x * b.x + a.y * b.y;
    a = cvt_h2(A1.w); b = cvt_h2(B1.w); dot += a.x * b.x + a.y * b.y;

    // MLP head: lane owns hidden units 2l, 2l+1 (b1 pre-folded into proj col-side)
    float2 pa = *(const float2*)(g_proj + (size_t)row * 32 + 2 * l);
    float2 pb = *(const float2*)(g_proj + (size_t)col * 32 + 16 + 2 * l);
    float2 w2 = *(const float2*)(W2 + 2 * l);
    float h0 = fmaxf(pa.x + pb.x, 0.f);
    float h1 = fmaxf(pa.y + pb.y, 0.f);
    float t  = h0 * w2.x + h1 * w2.y;

    #pragma unroll
    for (int off = 4; off; off >>= 1) {
        dot += __shfl_xor_sync(0xFFFFFFFFu, dot, off);
        t   += __shfl_xor_sync(0xFFFFFFFFu, t, off);
    }

    if (l == 0 && valid) {
        out[e] = dot;
        float x = t + __ldg(b2);
        // softplus = max(x,0) + log1p(exp(-|x|))
        out[(size_t)E + e] = fmaxf(x, 0.f) + log1pf(__expf(-fabsf(x)));
    }
}

// ---------------- launch ----------------------------------------------------
extern "C" void kernel_launch(void* const* d_in, const int* in_sizes, int n_in,
                              void* d_out, int out_size) {
    const float* z  = (const float*)d_in[0];      // [N,128] f32
    const int*   ei = (const int*)d_in[1];        // [2,E] int32
    const float* W1 = (const float*)d_in[2];      // [256,16]
    const float* b1 = (const float*)d_in[3];      // [16]
    const float* W2 = (const float*)d_in[4];      // [16,1]
    const float* b2 = (const float*)d_in[5];      // [1]
    float* out = (float*)d_out;                   // [2E]: adj_logits | weights

    const int N = in_sizes[0] / 128;
    const int E = in_sizes[1] / 2;

    proj_kernel<<<(N + NODES_PER_BLOCK - 1) / NODES_PER_BLOCK, PROJ_BLOCK>>>(z, W1, b1, N);
    edge_kernel<<<((size_t)E * 8 + 255) / 256, 256>>>(ei, W2, b2, out, E);
}